// round 6
// baseline (speedup 1.0000x reference)
#include <cuda_runtime.h>
#include <cuda_pipeline_primitives.h>

// Problem constants (fixed by the reference):
//   image 1000x1000, patch 5x5 -> 200x200 = 40000 patches
//   coefficients [40000, 3, 10, 2], bias [40000, 3]
//   out [3, 1000000]
#define IMG_W           1000
#define NUM_PIX         1000000
#define PATCH           5
#define PATCHES_PER_ROW 200
#define COEF_PER_PATCH  60          // 3*10*2
#define PB              40          // patches per tile (one fifth of a patch-row)
#define NTHREADS        256
#define NTILES          1000
#define GRID            500         // 2 tiles per block, software-pipelined
#define SM_STRIDE       68          // 60 padded to 68: 16B-aligned rows, conflict-free LDS.128

// Shared-memory layout (floats), per input stage:
//   sc: 40*68 = 2720   (coefficients, padded rows)
//   sb: 128            (bias, 120 used)
//   sp: 2000           (pixels: 5 rows x 200 px x 2)
#define SC_OFF          0
#define SB_OFF          2720
#define SP_OFF          2848
#define STAGE_F         4848        // floats per stage (16B multiple)
#define SO_OFF          (2 * STAGE_F)
#define SMEM_FLOATS     (2 * STAGE_F + 3000)
#define SMEM_BYTES      (SMEM_FLOATS * 4)   // 50784 B

// Packed dual-FP32 FMA (Blackwell)
__device__ __forceinline__ unsigned long long ffma2(unsigned long long a,
                                                    unsigned long long b,
                                                    unsigned long long c)
{
    unsigned long long d;
    asm("fma.rn.f32x2 %0, %1, %2, %3;" : "=l"(d) : "l"(a), "l"(b), "l"(c));
    return d;
}
__device__ __forceinline__ unsigned long long as_u64(double v)
{
    return __double_as_longlong(v);
}
__device__ __forceinline__ float hsum2(unsigned long long v)
{
    float lo, hi;
    asm("mov.b64 {%0, %1}, %2;" : "=f"(lo), "=f"(hi) : "l"(v));
    return lo + hi;
}

// Issue cp.async loads for one tile into the given stage buffer.
__device__ __forceinline__ void load_tile(int tile, float* buf, int tid,
                                          const float* __restrict__ pix,
                                          const float* __restrict__ coef,
                                          const float* __restrict__ bias)
{
    const int pr      = tile / 5;
    const int cb      = (tile - pr * 5) * PB;
    const int pbase   = pr * PATCHES_PER_ROW + cb;
    const int colBase = cb * PATCH;

    // Coefficients: 600 float4, contiguous in gmem -> padded rows in smem.
    const float4* g4 = (const float4*)(coef + (size_t)pbase * COEF_PER_PATCH);
    #pragma unroll
    for (int k = 0; k < 3; k++) {
        int idx = tid + k * NTHREADS;
        if (idx < 600) {
            int pp  = idx / 15;
            int off = idx - pp * 15;
            __pipeline_memcpy_async(&buf[SC_OFF + pp * SM_STRIDE + off * 4], &g4[idx], 16);
        }
    }
    // Bias: 30 float4 (pbase*3 floats is 480B-aligned).
    if (tid < 30)
        __pipeline_memcpy_async(&buf[SB_OFF + tid * 4],
                                (const float4*)(bias + (size_t)pbase * 3) + tid, 16);
    // Pixels: 5 rows x 100 float4, rows contiguous.
    const float4* p4 = (const float4*)pix;
    const int rowf4base = (pr * PATCH * IMG_W + colBase) >> 1;
    #pragma unroll
    for (int k = 0; k < 2; k++) {
        int idx = tid + k * NTHREADS;
        if (idx < 500) {
            int r   = idx / 100;
            int off = idx - r * 100;
            __pipeline_memcpy_async(&buf[SP_OFF + r * 400 + off * 4],
                                    &p4[rowf4base + r * (IMG_W / 2) + off], 16);
        }
    }
}

// Compute one tile from stage buffer into the shared output staging area.
__device__ __forceinline__ void compute_tile(const float* buf, float* so, int tid)
{
    if (tid >= PB * PATCH) return;
    const int p_local = tid % PB;
    const int seg     = tid / PB;

    unsigned long long xy[PATCH];
    {
        const double* ps = (const double*)&buf[SP_OFF + seg * 400 + p_local * 10];
        #pragma unroll
        for (int i = 0; i < PATCH; i++)
            xy[i] = as_u64(ps[i]);
    }

    const float* cc0 = &buf[SC_OFF + p_local * SM_STRIDE];

    #pragma unroll
    for (int ch = 0; ch < 3; ch++) {
        const double2* cp = (const double2*)(cc0 + ch * 20);
        const float bv = buf[SB_OFF + p_local * 3 + ch];

        unsigned long long acc[PATCH];
        {
            double2 v = cp[4];                       // pairs t=8, t=9
            const unsigned long long c8 = as_u64(v.x), c9 = as_u64(v.y);
            #pragma unroll
            for (int i = 0; i < PATCH; i++)
                acc[i] = ffma2(c9, xy[i], c8);
        }
        #pragma unroll
        for (int j = 3; j >= 0; j--) {
            double2 v = cp[j];                       // pairs t=2j, t=2j+1
            const unsigned long long clo = as_u64(v.x), chi = as_u64(v.y);
            #pragma unroll
            for (int i = 0; i < PATCH; i++)
                acc[i] = ffma2(acc[i], xy[i], chi);
            #pragma unroll
            for (int i = 0; i < PATCH; i++)
                acc[i] = ffma2(acc[i], xy[i], clo);
        }
        float* dst = &so[(ch * PATCH + seg) * (PB * PATCH) + p_local * PATCH];
        #pragma unroll
        for (int i = 0; i < PATCH; i++)
            dst[i] = hsum2(acc[i]) + bv;
    }
}

// Coalesced float4 copy of the staged tile to gmem.
__device__ __forceinline__ void store_tile(int tile, const float* so, int tid,
                                           float* __restrict__ out)
{
    const int pr      = tile / 5;
    const int colBase = (tile - pr * 5) * PB * PATCH;
    const float4* s4 = (const float4*)so;
    #pragma unroll
    for (int k = 0; k < 3; k++) {
        int j = tid + k * NTHREADS;
        if (j < 750) {
            int chseg = j / 50;
            int off   = j - chseg * 50;
            int ch    = chseg / PATCH;
            int seg   = chseg - ch * PATCH;
            int gfl   = ch * NUM_PIX + (pr * PATCH + seg) * IMG_W + colBase + off * 4;
            *(float4*)&out[gfl] = s4[j];
        }
    }
}

__global__ __launch_bounds__(NTHREADS, 4)
void ts_kernel(const float* __restrict__ pix,
               const float* __restrict__ coef,
               const float* __restrict__ bias,
               float* __restrict__ out)
{
    extern __shared__ float smem[];
    const int tid = threadIdx.x;
    const int b   = blockIdx.x;     // 0..499; handles tiles b and b+500

    // Prefetch both tiles (two commit groups).
    load_tile(b, smem, tid, pix, coef, bias);
    __pipeline_commit();
    load_tile(b + GRID, smem + STAGE_F, tid, pix, coef, bias);
    __pipeline_commit();

    float* so = smem + SO_OFF;

    // ---- Tile 0 ----
    __pipeline_wait_prior(1);
    __syncthreads();
    compute_tile(smem, so, tid);
    __syncthreads();
    store_tile(b, so, tid, out);

    // ---- Tile 1 (loads were in flight under tile-0 compute+store) ----
    __pipeline_wait_prior(0);
    __syncthreads();               // orders store-reads of so before overwrite
    compute_tile(smem + STAGE_F, so, tid);
    __syncthreads();
    store_tile(b + GRID, so, tid, out);
}

extern "C" void kernel_launch(void* const* d_in, const int* in_sizes, int n_in,
                              void* d_out, int out_size)
{
    const float* pix  = (const float*)d_in[0];   // [1000000, 2]
    const float* coef = (const float*)d_in[1];   // [40000, 3, 10, 2]
    const float* bias = (const float*)d_in[2];   // [40000, 3]
    float* out = (float*)d_out;                  // [3, 1000000]

    (void)in_sizes; (void)n_in; (void)out_size;
    cudaFuncSetAttribute(ts_kernel, cudaFuncAttributeMaxDynamicSharedMemorySize, SMEM_BYTES);
    ts_kernel<<<GRID, NTHREADS, SMEM_BYTES>>>(pix, coef, bias, out);
}

// round 8
// speedup vs baseline: 1.0156x; 1.0156x over previous
#include <cuda_runtime.h>
#include <cuda_pipeline_primitives.h>

// Problem constants (fixed by the reference):
//   image 1000x1000, patch 5x5 -> 200x200 = 40000 patches
//   coefficients [40000, 3, 10, 2], bias [40000, 3]
//   out [3, 1000000]
#define IMG_W           1000
#define NUM_PIX         1000000
#define PATCH           5
#define PATCHES_PER_ROW 200
#define COEF_PER_PATCH  60          // 3*10*2
#define PB              40          // patches per block (one fifth of a patch-row)
#define NTHREADS        256

// Packed dual-FP32 FMA (Blackwell)
__device__ __forceinline__ unsigned long long ffma2(unsigned long long a,
                                                    unsigned long long b,
                                                    unsigned long long c)
{
    unsigned long long d;
    asm("fma.rn.f32x2 %0, %1, %2, %3;" : "=l"(d) : "l"(a), "l"(b), "l"(c));
    return d;
}
__device__ __forceinline__ unsigned long long as_u64(double v)
{
    return __double_as_longlong(v);
}
__device__ __forceinline__ float hsum2(unsigned long long v)
{
    float lo, hi;
    asm("mov.b64 {%0, %1}, %2;" : "=f"(lo), "=f"(hi) : "l"(v));
    return lo + hi;
}

__global__ __launch_bounds__(NTHREADS, 6)
void ts_kernel(const float* __restrict__ pix,
               const float* __restrict__ coef,
               const float* __restrict__ bias,
               float* __restrict__ out)
{
    __shared__ float sc[PB * COEF_PER_PATCH];   // 2400 floats, LINEAR (9600 B)
    __shared__ float sb[128];                   // bias, 120 used (512 B)

    const int tid = threadIdx.x;
    const int b   = blockIdx.x;          // 0..999
    const int pr  = b / 5;               // patch row 0..199
    const int cb  = (b - pr * 5) * PB;   // patch-col base
    const int pbase   = pr * PATCHES_PER_ROW + cb;
    const int colBase = cb * PATCH;      // pixel column base (multiple of 200)

    // ---- Coefficient + bias staging: straight linear cp.async copy ----
    {
        const float4* g4 = (const float4*)(coef + (size_t)pbase * COEF_PER_PATCH);
        #pragma unroll
        for (int k = 0; k < 3; k++) {
            int idx = tid + k * NTHREADS;
            if (idx < 600)
                __pipeline_memcpy_async(&sc[idx * 4], &g4[idx], 16);
        }
        if (tid < 30)
            __pipeline_memcpy_async(&sb[tid * 4],
                                    (const float4*)(bias + (size_t)pbase * 3) + tid, 16);
        __pipeline_commit();
    }

    // ---- Early pixel loads (independent of smem; overlap the coeff wait) ----
    const int p_local = tid % PB;        // 0..39
    const int seg     = tid / PB;        // 0..7 (only 0..4 compute)
    const int pixBase = (pr * PATCH + seg) * IMG_W + colBase + p_local * PATCH;

    unsigned long long xy[PATCH];
    if (tid < PB * PATCH) {
        const double* pp8 = (const double*)pix + pixBase;   // pixel n = double n
        #pragma unroll
        for (int i = 0; i < PATCH; i++)
            xy[i] = as_u64(pp8[i]);
    }

    __pipeline_wait_prior(0);
    __syncthreads();

    // ---- Compute + direct stores (200 threads; thread = 5-pixel segment) ----
    if (tid < PB * PATCH) {
        const float* cc0 = &sc[p_local * COEF_PER_PATCH];   // 240B stride: conflict-free
        const float bv0 = sb[p_local * 3 + 0];
        const float bv1 = sb[p_local * 3 + 1];
        const float bv2 = sb[p_local * 3 + 2];
        float* o = out + pixBase;

        #pragma unroll
        for (int ch = 0; ch < 3; ch++) {
            const double2* cp = (const double2*)(cc0 + ch * 20);  // 16B-aligned
            const float bv = (ch == 0) ? bv0 : (ch == 1) ? bv1 : bv2;

            unsigned long long acc[PATCH];
            {
                double2 v = cp[4];                       // pairs t=8, t=9
                const unsigned long long c8 = as_u64(v.x), c9 = as_u64(v.y);
                #pragma unroll
                for (int i = 0; i < PATCH; i++)
                    acc[i] = ffma2(c9, xy[i], c8);
            }
            #pragma unroll
            for (int j = 3; j >= 0; j--) {
                double2 v = cp[j];                       // pairs t=2j, t=2j+1
                const unsigned long long clo = as_u64(v.x), chi = as_u64(v.y);
                #pragma unroll
                for (int i = 0; i < PATCH; i++)
                    acc[i] = ffma2(acc[i], xy[i], chi);
                #pragma unroll
                for (int i = 0; i < PATCH; i++)
                    acc[i] = ffma2(acc[i], xy[i], clo);
            }
            float* oc = o + ch * NUM_PIX;
            #pragma unroll
            for (int i = 0; i < PATCH; i++)
                oc[i] = hsum2(acc[i]) + bv;              // warp run: contiguous 640B
        }
    }
}

extern "C" void kernel_launch(void* const* d_in, const int* in_sizes, int n_in,
                              void* d_out, int out_size)
{
    const float* pix  = (const float*)d_in[0];   // [1000000, 2]
    const float* coef = (const float*)d_in[1];   // [40000, 3, 10, 2]
    const float* bias = (const float*)d_in[2];   // [40000, 3]
    float* out = (float*)d_out;                  // [3, 1000000]

    (void)in_sizes; (void)n_in; (void)out_size;
    ts_kernel<<<1000, NTHREADS>>>(pix, coef, bias, out);
}